// round 1
// baseline (speedup 1.0000x reference)
#include <cuda_runtime.h>
#include <cstdint>
#include <cstddef>

#define B 8
#define L 2048
#define E 128
#define KC 16
#define BM 128
#define BN 128

// ---------------- scratch (device globals: no allocation allowed) ----------
__device__ float g_S[(size_t)B * L * L];     // 134 MB: masked logits S[b][i][j]
__device__ float g_T[(size_t)B * L * E];     // T = P^T @ Uid
__device__ float g_sid[B * L];
__device__ float g_sq[B * L];
__device__ float g_invd[B * L];              // 1 / sum_i exp(S[i][j])

// ---------------- packed f32x2 helpers (Blackwell FFMA2) -------------------
__device__ __forceinline__ unsigned long long pk2(float lo, float hi) {
    unsigned long long r;
    asm("mov.b64 %0, {%1, %2};" : "=l"(r) : "f"(lo), "f"(hi));
    return r;
}
__device__ __forceinline__ float2 upk2(unsigned long long v) {
    float2 r;
    asm("mov.b64 {%0, %1}, %2;" : "=f"(r.x), "=f"(r.y) : "l"(v));
    return r;
}
__device__ __forceinline__ unsigned long long ffma2(unsigned long long a,
                                                    unsigned long long b,
                                                    unsigned long long c) {
    unsigned long long d;
    asm("fma.rn.f32x2 %0, %1, %2, %3;" : "=l"(d) : "l"(a), "l"(b), "l"(c));
    return d;
}

// 8x8 per-thread microkernel over one KC chunk. As/Bs row pitch in floats.
template <int PITCH_A, int PITCH_B>
__device__ __forceinline__ void micro8x8(const float* __restrict__ As,
                                         const float* __restrict__ Bs,
                                         int ty, int tx,
                                         unsigned long long acc[8][4]) {
#pragma unroll
    for (int kk = 0; kk < KC; kk++) {
        __align__(16) float a[8];
        *(float4*)&a[0] = *(const float4*)&As[kk * PITCH_A + ty * 8];
        *(float4*)&a[4] = *(const float4*)&As[kk * PITCH_A + ty * 8 + 4];
        ulonglong2 b0 = *(const ulonglong2*)&Bs[kk * PITCH_B + tx * 8];
        ulonglong2 b1 = *(const ulonglong2*)&Bs[kk * PITCH_B + tx * 8 + 4];
        unsigned long long bv[4] = {b0.x, b0.y, b1.x, b1.y};
#pragma unroll
        for (int m = 0; m < 8; m++) {
            unsigned long long av = pk2(a[m], a[m]);
#pragma unroll
            for (int p = 0; p < 4; p++) acc[m][p] = ffma2(av, bv[p], acc[m][p]);
        }
    }
}

// ---------------- kernel 1: row dots s_id, s_q ------------------------------
__global__ void k_dots(const float* __restrict__ Uq,
                       const float* __restrict__ Uid,
                       const float* __restrict__ Wc_w) {
    int r = blockIdx.x * 8 + threadIdx.y;  // 0 .. B*L-1
    int lane = threadIdx.x;
    float sid = 0.f, sq = 0.f;
#pragma unroll
    for (int t = 0; t < 4; t++) {
        int e = lane + t * 32;
        sid += Uid[(size_t)r * E + e] * Wc_w[e];       // w_id
        sq  += Uq [(size_t)r * E + e] * Wc_w[E + e];   // w_q
    }
#pragma unroll
    for (int o = 16; o; o >>= 1) {
        sid += __shfl_xor_sync(0xffffffffu, sid, o);
        sq  += __shfl_xor_sync(0xffffffffu, sq,  o);
    }
    if (lane == 0) { g_sid[r] = sid; g_sq[r] = sq; }
}

// ---------------- kernel 2: S = (sid+sq+ (Uid*wmul)Uq^T + b) * mask ---------
__global__ __launch_bounds__(256) void k_sgemm(const float* __restrict__ Uq,
                                               const float* __restrict__ Uid,
                                               const float* __restrict__ mask,
                                               const float* __restrict__ Wc_w,
                                               const float* __restrict__ Wc_b) {
    __shared__ float As[KC][BM + 4];
    __shared__ float Bs[KC][BN + 4];
    int b  = blockIdx.z;
    int i0 = blockIdx.y * BM;
    int j0 = blockIdx.x * BN;
    const float* A  = Uid + (size_t)b * L * E;
    const float* Bq = Uq  + (size_t)b * L * E;
    const float* wmul = Wc_w + 2 * E;
    int tid = threadIdx.x;
    int tx = tid & 15, ty = tid >> 4;

    unsigned long long acc[8][4];
#pragma unroll
    for (int m = 0; m < 8; m++)
#pragma unroll
        for (int p = 0; p < 4; p++) acc[m][p] = 0ull;

    for (int k0 = 0; k0 < E; k0 += KC) {
#pragma unroll
        for (int s = 0; s < 2; s++) {
            int f = tid + s * 256;
            int row = f >> 2, kq = (f & 3) * 4;
            float4 va = *(const float4*)&A[(size_t)(i0 + row) * E + k0 + kq];
            va.x *= wmul[k0 + kq];     va.y *= wmul[k0 + kq + 1];
            va.z *= wmul[k0 + kq + 2]; va.w *= wmul[k0 + kq + 3];
            As[kq][row] = va.x; As[kq + 1][row] = va.y;
            As[kq + 2][row] = va.z; As[kq + 3][row] = va.w;
            float4 vb = *(const float4*)&Bq[(size_t)(j0 + row) * E + k0 + kq];
            Bs[kq][row] = vb.x; Bs[kq + 1][row] = vb.y;
            Bs[kq + 2][row] = vb.z; Bs[kq + 3][row] = vb.w;
        }
        __syncthreads();
        micro8x8<BM + 4, BN + 4>(&As[0][0], &Bs[0][0], ty, tx, acc);
        __syncthreads();
    }

    float bias = *Wc_b;
    float* Sout = g_S + (size_t)b * L * L;
#pragma unroll
    for (int m = 0; m < 8; m++) {
        int gi = i0 + ty * 8 + m;
        float sid = g_sid[b * L + gi];
#pragma unroll
        for (int p = 0; p < 4; p++) {
            int gj = j0 + tx * 8 + p * 2;
            float2 v   = upk2(acc[m][p]);
            float2 sq2 = *(const float2*)&g_sq[b * L + gj];
            float2 mk  = *(const float2*)&mask[(size_t)gi * L + gj];
            float r0 = (v.x + sid + sq2.x + bias) * mk.x;
            float r1 = (v.y + sid + sq2.y + bias) * mk.y;
            *(float2*)&Sout[(size_t)gi * L + gj] = make_float2(r0, r1);
        }
    }
}

// ---------------- kernel 3: column softmax denominators --------------------
// invd[b][j] = 1 / sum_i exp(S[b][i][j]).  S bounded (~|6|): no max needed.
__global__ __launch_bounds__(256) void k_stats() {
    int b = blockIdx.z;
    int tid = threadIdx.x;
    int tx = tid & 63, ty = tid >> 6;          // 64 columns x 4 row-slices
    int j = blockIdx.x * 64 + tx;
    const float* p = g_S + (size_t)b * L * L + (size_t)ty * 512 * L + j;
    float d0 = 0.f, d1 = 0.f, d2 = 0.f, d3 = 0.f;
    for (int i = 0; i < 512; i += 4) {
        d0 += __expf(p[(size_t)(i + 0) * L]);
        d1 += __expf(p[(size_t)(i + 1) * L]);
        d2 += __expf(p[(size_t)(i + 2) * L]);
        d3 += __expf(p[(size_t)(i + 3) * L]);
    }
    __shared__ float sred[4][64];
    sred[ty][tx] = (d0 + d1) + (d2 + d3);
    __syncthreads();
    if (ty == 0) {
        float tot = sred[0][tx] + sred[1][tx] + sred[2][tx] + sred[3][tx];
        g_invd[b * L + j] = 1.0f / tot;
    }
}

// ---------------- kernel 4: T[j][e] = invd[j] * sum_i exp(S[i][j]) Uid[i][e]
// BM=64 rows (j), BN=128 cols (e), 4x8 per thread, K = i = 2048.
__global__ __launch_bounds__(256) void k_tgemm(const float* __restrict__ Uid) {
    __shared__ float As[KC][64 + 4];
    __shared__ float Bs[KC][BN + 4];
    int b = blockIdx.z;
    int j0 = blockIdx.x * 64;
    const float* Sb = g_S + (size_t)b * L * L;
    const float* Ub = Uid + (size_t)b * L * E;
    int tid = threadIdx.x;
    int tx = tid & 15, ty = tid >> 4;

    unsigned long long acc[4][4];
#pragma unroll
    for (int m = 0; m < 4; m++)
#pragma unroll
        for (int p = 0; p < 4; p++) acc[m][p] = 0ull;

    for (int k0 = 0; k0 < L; k0 += KC) {
        {   // A chunk: 16 (i) x 64 (j), exp applied, no transpose needed
            int row = tid >> 4;            // k (i-local)
            int cq  = (tid & 15) * 4;      // j-local
            float4 v = *(const float4*)&Sb[(size_t)(k0 + row) * L + j0 + cq];
            As[row][cq]     = __expf(v.x);
            As[row][cq + 1] = __expf(v.y);
            As[row][cq + 2] = __expf(v.z);
            As[row][cq + 3] = __expf(v.w);
        }
#pragma unroll
        for (int s = 0; s < 2; s++) {      // B chunk: 16 (i) x 128 (e) copy
            int f = tid + s * 256;
            int row = f >> 5, eq = (f & 31) * 4;
            *(float4*)&Bs[row][eq] =
                *(const float4*)&Ub[(size_t)(k0 + row) * E + eq];
        }
        __syncthreads();
#pragma unroll
        for (int kk = 0; kk < KC; kk++) {
            __align__(16) float a[4];
            *(float4*)&a[0] = *(const float4*)&As[kk][ty * 4];
            ulonglong2 b0 = *(const ulonglong2*)&Bs[kk][tx * 8];
            ulonglong2 b1 = *(const ulonglong2*)&Bs[kk][tx * 8 + 4];
            unsigned long long bv[4] = {b0.x, b0.y, b1.x, b1.y};
#pragma unroll
            for (int m = 0; m < 4; m++) {
                unsigned long long av = pk2(a[m], a[m]);
#pragma unroll
                for (int p = 0; p < 4; p++) acc[m][p] = ffma2(av, bv[p], acc[m][p]);
            }
        }
        __syncthreads();
    }

#pragma unroll
    for (int m = 0; m < 4; m++) {
        int gj = j0 + ty * 4 + m;
        float inv = g_invd[b * L + gj];
        float* Trow = g_T + ((size_t)b * L + gj) * E + tx * 8;
#pragma unroll
        for (int p = 0; p < 4; p++) {
            float2 v = upk2(acc[m][p]);
            *(float2*)&Trow[p * 2] = make_float2(v.x * inv, v.y * inv);
        }
    }
}

// ---------------- kernel 5: A = P @ [Uq | T], fused concat epilogue --------
// blockIdx.x: 0 -> V=Uq (A_D2Q half), 1 -> V=T (A_Q2D half)
__global__ __launch_bounds__(256) void k_final(const float* __restrict__ Uq,
                                               const float* __restrict__ Uid,
                                               float* __restrict__ out) {
    __shared__ float As[KC][BM + 4];
    __shared__ float Bs[KC][BN + 4];
    int b  = blockIdx.z;
    int i0 = blockIdx.y * BM;
    int nt = blockIdx.x;
    const float* Sb = g_S + (size_t)b * L * L;
    const float* V  = nt ? (g_T + (size_t)b * L * E) : (Uq + (size_t)b * L * E);
    int tid = threadIdx.x;
    int tx = tid & 15, ty = tid >> 4;

    unsigned long long acc[8][4];
#pragma unroll
    for (int m = 0; m < 8; m++)
#pragma unroll
        for (int p = 0; p < 4; p++) acc[m][p] = 0ull;

    for (int k0 = 0; k0 < L; k0 += KC) {
#pragma unroll
        for (int s = 0; s < 2; s++) {
            int f = tid + s * 256;
            // A chunk: P[i][j] tile, transposed into As[k=j][i], exp*invd
            int row = f >> 2, kq = (f & 3) * 4;
            float4 v = *(const float4*)&Sb[(size_t)(i0 + row) * L + k0 + kq];
            As[kq][row]     = __expf(v.x) * g_invd[b * L + k0 + kq];
            As[kq + 1][row] = __expf(v.y) * g_invd[b * L + k0 + kq + 1];
            As[kq + 2][row] = __expf(v.z) * g_invd[b * L + k0 + kq + 2];
            As[kq + 3][row] = __expf(v.w) * g_invd[b * L + k0 + kq + 3];
            // B chunk: V rows (j) x 128 (e), straight copy
            int rowb = f >> 5, eq = (f & 31) * 4;
            *(float4*)&Bs[rowb][eq] =
                *(const float4*)&V[(size_t)(k0 + rowb) * E + eq];
        }
        __syncthreads();
        micro8x8<BM + 4, BN + 4>(&As[0][0], &Bs[0][0], ty, tx, acc);
        __syncthreads();
    }

    // out layout per row i: [Uid(0:128) | A_D2Q(128:256) | Uid*A_D2Q(256:384) | Uid*A_Q2D(384:512)]
#pragma unroll
    for (int m = 0; m < 8; m++) {
        int gi = i0 + ty * 8 + m;
        int n0 = tx * 8;
        const float* urow = Uid + ((size_t)b * L + gi) * E + n0;
        __align__(16) float u[8], r[8], q[8];
        *(float4*)&u[0] = *(const float4*)&urow[0];
        *(float4*)&u[4] = *(const float4*)&urow[4];
#pragma unroll
        for (int p = 0; p < 4; p++) {
            float2 v = upk2(acc[m][p]);
            r[p * 2] = v.x; r[p * 2 + 1] = v.y;
        }
#pragma unroll
        for (int c = 0; c < 8; c++) q[c] = u[c] * r[c];
        float* orow = out + ((size_t)b * L + gi) * (4 * E);
        if (nt == 0) {
            *(float4*)&orow[128 + n0]     = *(float4*)&r[0];
            *(float4*)&orow[128 + n0 + 4] = *(float4*)&r[4];
            *(float4*)&orow[256 + n0]     = *(float4*)&q[0];
            *(float4*)&orow[256 + n0 + 4] = *(float4*)&q[4];
        } else {
            *(float4*)&orow[n0]           = *(float4*)&u[0];
            *(float4*)&orow[n0 + 4]       = *(float4*)&u[4];
            *(float4*)&orow[384 + n0]     = *(float4*)&q[0];
            *(float4*)&orow[384 + n0 + 4] = *(float4*)&q[4];
        }
    }
}

// ---------------- launch ----------------------------------------------------
extern "C" void kernel_launch(void* const* d_in, const int* in_sizes, int n_in,
                              void* d_out, int out_size) {
    const float* Uq   = (const float*)d_in[0];
    const float* Uid  = (const float*)d_in[1];
    const float* mask = (const float*)d_in[2];
    const float* Wc_w = (const float*)d_in[3];
    const float* Wc_b = (const float*)d_in[4];
    float* out = (float*)d_out;

    k_dots<<<(B * L) / 8, dim3(32, 8)>>>(Uq, Uid, Wc_w);
    k_sgemm<<<dim3(L / BN, L / BM, B), 256>>>(Uq, Uid, mask, Wc_w, Wc_b);
    k_stats<<<dim3(L / 64, 1, B), 256>>>();
    k_tgemm<<<dim3(L / 64, 1, B), 256>>>(Uid);
    k_final<<<dim3(2, L / BM, B), 256>>>(Uq, Uid, out);
}

// round 2
// speedup vs baseline: 1.2856x; 1.2856x over previous
#include <cuda_runtime.h>
#include <cstdint>
#include <cstddef>

#define B 8
#define L 2048
#define E 128
#define KC 16
#define BM 128
#define BN 128
#define PAF 20

// ---------------- scratch (device globals: no allocation allowed) ----------
__device__ float g_S[(size_t)B * L * L];     // exp(S*mask)  (unnormalized P)
__device__ float g_T[(size_t)B * L * E];     // T' = invd^2 * (expS^T @ Uid)
__device__ float g_Uqs[(size_t)B * L * E];   // Uq' = invd * Uq
__device__ float g_sid[B * L];
__device__ float g_sq[B * L];
__device__ float g_d[B * L];                 // column sums of expS
__device__ float g_invd[B * L];

// ---------------- packed f32x2 helpers (Blackwell FFMA2) -------------------
__device__ __forceinline__ unsigned long long pk2(float lo, float hi) {
    unsigned long long r;
    asm("mov.b64 %0, {%1, %2};" : "=l"(r) : "f"(lo), "f"(hi));
    return r;
}
__device__ __forceinline__ float2 upk2(unsigned long long v) {
    float2 r;
    asm("mov.b64 {%0, %1}, %2;" : "=f"(r.x), "=f"(r.y) : "l"(v));
    return r;
}
__device__ __forceinline__ unsigned long long ffma2(unsigned long long a,
                                                    unsigned long long b,
                                                    unsigned long long c) {
    unsigned long long d;
    asm("fma.rn.f32x2 %0, %1, %2, %3;" : "=l"(d) : "l"(a), "l"(b), "l"(c));
    return d;
}

// ---------------- cp.async helpers -----------------------------------------
__device__ __forceinline__ uint32_t sptr(const void* p) {
    return (uint32_t)__cvta_generic_to_shared(p);
}
__device__ __forceinline__ void cpa16(uint32_t dst, const float* src) {
    asm volatile("cp.async.cg.shared.global [%0], [%1], 16;"
                 :: "r"(dst), "l"(src) : "memory");
}
__device__ __forceinline__ void cpa_commit() {
    asm volatile("cp.async.commit_group;" ::: "memory");
}
__device__ __forceinline__ void cpa_wait1() {
    asm volatile("cp.async.wait_group 1;" ::: "memory");
}
__device__ __forceinline__ void cpa_wait0() {
    asm volatile("cp.async.wait_group 0;" ::: "memory");
}

// 8x8 per-thread microkernel over one KC chunk, A and B both k-major.
template <int PITCH_A, int PITCH_B>
__device__ __forceinline__ void micro8x8(const float* __restrict__ As,
                                         const float* __restrict__ Bs,
                                         int ty, int tx,
                                         unsigned long long acc[8][4]) {
#pragma unroll
    for (int kk = 0; kk < KC; kk++) {
        __align__(16) float a[8];
        *(float4*)&a[0] = *(const float4*)&As[kk * PITCH_A + ty * 8];
        *(float4*)&a[4] = *(const float4*)&As[kk * PITCH_A + ty * 8 + 4];
        ulonglong2 b0 = *(const ulonglong2*)&Bs[kk * PITCH_B + tx * 8];
        ulonglong2 b1 = *(const ulonglong2*)&Bs[kk * PITCH_B + tx * 8 + 4];
        unsigned long long bv[4] = {b0.x, b0.y, b1.x, b1.y};
#pragma unroll
        for (int m = 0; m < 8; m++) {
            unsigned long long av = pk2(a[m], a[m]);
#pragma unroll
            for (int p = 0; p < 4; p++) acc[m][p] = ffma2(av, bv[p], acc[m][p]);
        }
    }
}

__device__ __forceinline__ float f4get(const float4& v, int q) {
    return q == 0 ? v.x : (q == 1 ? v.y : (q == 2 ? v.z : v.w));
}

// ---------------- kernel 1: row dots s_id, s_q + zero g_d -------------------
__global__ void k_dots(const float* __restrict__ Uq,
                       const float* __restrict__ Uid,
                       const float* __restrict__ Wc_w) {
    int r = blockIdx.x * 8 + threadIdx.y;  // 0 .. B*L-1
    int lane = threadIdx.x;
    float sid = 0.f, sq = 0.f;
#pragma unroll
    for (int t = 0; t < 4; t++) {
        int e = lane + t * 32;
        sid += Uid[(size_t)r * E + e] * Wc_w[e];
        sq  += Uq [(size_t)r * E + e] * Wc_w[E + e];
    }
#pragma unroll
    for (int o = 16; o; o >>= 1) {
        sid += __shfl_xor_sync(0xffffffffu, sid, o);
        sq  += __shfl_xor_sync(0xffffffffu, sq,  o);
    }
    if (lane == 0) { g_sid[r] = sid; g_sq[r] = sq; g_d[r] = 0.f; }
}

// ---------------- kernel 2: expS = exp((sid+sq+(Uid*wmul)Uq^T+b)*mask) ------
// Also accumulates column sums d[j] via smem + global atomics.
__global__ __launch_bounds__(256) void k_sgemm(const float* __restrict__ Uq,
                                               const float* __restrict__ Uid,
                                               const float* __restrict__ mask,
                                               const float* __restrict__ Wc_w,
                                               const float* __restrict__ Wc_b) {
    __shared__ float As[KC][BM + 4];
    __shared__ float Bs[KC][BN + 4];
    __shared__ float red[BN];
    int b  = blockIdx.z;
    int i0 = blockIdx.y * BM;
    int j0 = blockIdx.x * BN;
    const float* A  = Uid + (size_t)b * L * E;
    const float* Bq = Uq  + (size_t)b * L * E;
    const float* wmul = Wc_w + 2 * E;
    int tid = threadIdx.x;
    int tx = tid & 15, ty = tid >> 4;

    unsigned long long acc[8][4];
#pragma unroll
    for (int m = 0; m < 8; m++)
#pragma unroll
        for (int p = 0; p < 4; p++) acc[m][p] = 0ull;

    for (int k0 = 0; k0 < E; k0 += KC) {
#pragma unroll
        for (int s = 0; s < 2; s++) {
            int f = tid + s * 256;
            int row = f >> 2, kq = (f & 3) * 4;
            float4 va = *(const float4*)&A[(size_t)(i0 + row) * E + k0 + kq];
            va.x *= wmul[k0 + kq];     va.y *= wmul[k0 + kq + 1];
            va.z *= wmul[k0 + kq + 2]; va.w *= wmul[k0 + kq + 3];
            As[kq][row] = va.x; As[kq + 1][row] = va.y;
            As[kq + 2][row] = va.z; As[kq + 3][row] = va.w;
            float4 vb = *(const float4*)&Bq[(size_t)(j0 + row) * E + k0 + kq];
            Bs[kq][row] = vb.x; Bs[kq + 1][row] = vb.y;
            Bs[kq + 2][row] = vb.z; Bs[kq + 3][row] = vb.w;
        }
        __syncthreads();
        micro8x8<BM + 4, BN + 4>(&As[0][0], &Bs[0][0], ty, tx, acc);
        __syncthreads();
    }

    if (tid < BN) red[tid] = 0.f;
    float bias = *Wc_b;
    float* Sout = g_S + (size_t)b * L * L;
    float colsum[8];
#pragma unroll
    for (int c = 0; c < 8; c++) colsum[c] = 0.f;
#pragma unroll
    for (int m = 0; m < 8; m++) {
        int gi = i0 + ty * 8 + m;
        float sid = g_sid[b * L + gi];
        __align__(16) float ev[8];
#pragma unroll
        for (int p = 0; p < 4; p++) {
            int gj = j0 + tx * 8 + p * 2;
            float2 v   = upk2(acc[m][p]);
            float2 sq2 = *(const float2*)&g_sq[b * L + gj];
            float2 mk  = *(const float2*)&mask[(size_t)gi * L + gj];
            float e0 = __expf((v.x + sid + sq2.x + bias) * mk.x);
            float e1 = __expf((v.y + sid + sq2.y + bias) * mk.y);
            ev[p * 2] = e0; ev[p * 2 + 1] = e1;
            colsum[p * 2] += e0; colsum[p * 2 + 1] += e1;
        }
        float* dst = &Sout[(size_t)gi * L + j0 + tx * 8];
        *(float4*)&dst[0] = *(float4*)&ev[0];
        *(float4*)&dst[4] = *(float4*)&ev[4];
    }
    __syncthreads();
#pragma unroll
    for (int c = 0; c < 8; c++) atomicAdd(&red[tx * 8 + c], colsum[c]);
    __syncthreads();
    if (tid < BN) atomicAdd(&g_d[(size_t)b * L + j0 + tid], red[tid]);
}

// ---------------- kernel 3: invd = 1/d ; Uq' = invd * Uq --------------------
__global__ __launch_bounds__(256) void k_scale(const float* __restrict__ Uq) {
    int r = blockIdx.x * 2 + (threadIdx.x >> 7);
    int e = threadIdx.x & 127;
    float inv = 1.0f / g_d[r];
    if (e == 0) g_invd[r] = inv;
    g_Uqs[(size_t)r * E + e] = inv * Uq[(size_t)r * E + e];
}

// ---------------- kernel 4: T' = invd^2 * (expS^T @ Uid) --------------------
// 128 (j) x 128 (e) tile, K = i = 2048, double-buffered cp.async.
__global__ __launch_bounds__(256) void k_tgemm(const float* __restrict__ Uid) {
    __shared__ float As[2][KC][BN + 4];
    __shared__ float Bs[2][KC][BN + 4];
    int b  = blockIdx.z;
    int j0 = blockIdx.x * 128;
    const float* Sb = g_S + (size_t)b * L * L;
    const float* Ub = Uid + (size_t)b * L * E;
    int tid = threadIdx.x, tx = tid & 15, ty = tid >> 4;

    const uint32_t stage = KC * (BN + 4) * 4;
    uint32_t aB = sptr(&As[0][0][0]) + (ty * (BN + 4) + tx * 8) * 4;
    uint32_t bB = sptr(&Bs[0][0][0]) + (ty * (BN + 4) + tx * 8) * 4;
    const float* gA = Sb + (size_t)ty * L + j0 + tx * 8;
    const float* gB = Ub + (size_t)ty * E + tx * 8;

    unsigned long long acc[8][4];
#pragma unroll
    for (int m = 0; m < 8; m++)
#pragma unroll
        for (int p = 0; p < 4; p++) acc[m][p] = 0ull;

    auto issue = [&](int s, int t) {
        const float* a = gA + (size_t)t * KC * L;
        cpa16(aB + s * stage, a);
        cpa16(aB + s * stage + 16, a + 4);
        const float* bb = gB + (size_t)t * KC * E;
        cpa16(bB + s * stage, bb);
        cpa16(bB + s * stage + 16, bb + 4);
        cpa_commit();
    };

    issue(0, 0);
    const int iters = L / KC;
    for (int t = 0; t < iters; t++) {
        int cur = t & 1;
        if (t + 1 < iters) { issue(cur ^ 1, t + 1); cpa_wait1(); }
        else               { cpa_wait0(); }
        __syncthreads();
        micro8x8<BN + 4, BN + 4>(&As[cur][0][0], &Bs[cur][0][0], ty, tx, acc);
        __syncthreads();
    }

#pragma unroll
    for (int m = 0; m < 8; m++) {
        int gj = j0 + ty * 8 + m;
        float inv = g_invd[b * L + gj];
        float s = inv * inv;
        float* Tr = g_T + ((size_t)b * L + gj) * E + tx * 8;
        __align__(16) float o[8];
#pragma unroll
        for (int p = 0; p < 4; p++) {
            float2 v = upk2(acc[m][p]);
            o[p * 2] = v.x * s; o[p * 2 + 1] = v.y * s;
        }
        *(float4*)&Tr[0] = *(float4*)&o[0];
        *(float4*)&Tr[4] = *(float4*)&o[4];
    }
}

// ---------------- kernel 5: [A_D2Q | A_Q2D] = expS @ [Uq' | T'] -------------
// A is m-major in gmem -> smem tile [i][k] pitch PAF, float4-over-k reads.
__global__ __launch_bounds__(256) void k_final(const float* __restrict__ Uid,
                                               float* __restrict__ out) {
    __shared__ float Af[2][BM][PAF];
    __shared__ float Bs[2][KC][BN + 4];
    int b  = blockIdx.z;
    int i0 = blockIdx.y * BM;
    int nt = blockIdx.x;
    const float* Sb = g_S + (size_t)b * L * L;
    const float* V  = nt ? (g_T + (size_t)b * L * E) : (g_Uqs + (size_t)b * L * E);
    int tid = threadIdx.x, tx = tid & 15, ty = tid >> 4;

    const uint32_t stageA = BM * PAF * 4;
    const uint32_t stageB = KC * (BN + 4) * 4;
    int ar = tid >> 1, ac = (tid & 1) * 8;
    uint32_t aB = sptr(&Af[0][0][0]) + (ar * PAF + ac) * 4;
    uint32_t bB = sptr(&Bs[0][0][0]) + (ty * (BN + 4) + tx * 8) * 4;
    const float* gA = Sb + (size_t)(i0 + ar) * L + ac;
    const float* gB = V + (size_t)ty * E + tx * 8;

    unsigned long long acc[8][4];
#pragma unroll
    for (int m = 0; m < 8; m++)
#pragma unroll
        for (int p = 0; p < 4; p++) acc[m][p] = 0ull;

    auto issue = [&](int s, int t) {
        const float* a = gA + t * KC;
        cpa16(aB + s * stageA, a);
        cpa16(aB + s * stageA + 16, a + 4);
        const float* bb = gB + (size_t)t * KC * E;
        cpa16(bB + s * stageB, bb);
        cpa16(bB + s * stageB + 16, bb + 4);
        cpa_commit();
    };

    issue(0, 0);
    const int iters = L / KC;
    for (int t = 0; t < iters; t++) {
        int cur = t & 1;
        if (t + 1 < iters) { issue(cur ^ 1, t + 1); cpa_wait1(); }
        else               { cpa_wait0(); }
        __syncthreads();
#pragma unroll
        for (int kk4 = 0; kk4 < KC / 4; kk4++) {
            float4 a4[8];
#pragma unroll
            for (int m = 0; m < 8; m++)
                a4[m] = *(const float4*)&Af[cur][ty * 8 + m][kk4 * 4];
#pragma unroll
            for (int q = 0; q < 4; q++) {
                const float* br = &Bs[cur][kk4 * 4 + q][tx * 8];
                ulonglong2 b0 = *(const ulonglong2*)&br[0];
                ulonglong2 b1 = *(const ulonglong2*)&br[4];
                unsigned long long bv[4] = {b0.x, b0.y, b1.x, b1.y};
#pragma unroll
                for (int m = 0; m < 8; m++) {
                    float aq = f4get(a4[m], q);
                    unsigned long long av = pk2(aq, aq);
#pragma unroll
                    for (int p = 0; p < 4; p++)
                        acc[m][p] = ffma2(av, bv[p], acc[m][p]);
                }
            }
        }
        __syncthreads();
    }

    // out row i: [Uid | A_D2Q | Uid*A_D2Q | Uid*A_Q2D]
#pragma unroll
    for (int m = 0; m < 8; m++) {
        int gi = i0 + ty * 8 + m;
        int n0 = tx * 8;
        const float* urow = Uid + ((size_t)b * L + gi) * E + n0;
        __align__(16) float u[8], r[8], q[8];
        *(float4*)&u[0] = *(const float4*)&urow[0];
        *(float4*)&u[4] = *(const float4*)&urow[4];
#pragma unroll
        for (int p = 0; p < 4; p++) {
            float2 v = upk2(acc[m][p]);
            r[p * 2] = v.x; r[p * 2 + 1] = v.y;
        }
#pragma unroll
        for (int c = 0; c < 8; c++) q[c] = u[c] * r[c];
        float* orow = out + ((size_t)b * L + gi) * (4 * E);
        if (nt == 0) {
            *(float4*)&orow[128 + n0]     = *(float4*)&r[0];
            *(float4*)&orow[128 + n0 + 4] = *(float4*)&r[4];
            *(float4*)&orow[256 + n0]     = *(float4*)&q[0];
            *(float4*)&orow[256 + n0 + 4] = *(float4*)&q[4];
        } else {
            *(float4*)&orow[n0]           = *(float4*)&u[0];
            *(float4*)&orow[n0 + 4]       = *(float4*)&u[4];
            *(float4*)&orow[384 + n0]     = *(float4*)&q[0];
            *(float4*)&orow[384 + n0 + 4] = *(float4*)&q[4];
        }
    }
}

// ---------------- launch ----------------------------------------------------
extern "C" void kernel_launch(void* const* d_in, const int* in_sizes, int n_in,
                              void* d_out, int out_size) {
    const float* Uq   = (const float*)d_in[0];
    const float* Uid  = (const float*)d_in[1];
    const float* mask = (const float*)d_in[2];
    const float* Wc_w = (const float*)d_in[3];
    const float* Wc_b = (const float*)d_in[4];
    float* out = (float*)d_out;

    k_dots<<<(B * L) / 8, dim3(32, 8)>>>(Uq, Uid, Wc_w);
    k_sgemm<<<dim3(L / BN, L / BM, B), 256>>>(Uq, Uid, mask, Wc_w, Wc_b);
    k_scale<<<(B * L) / 2, 256>>>(Uq);
    k_tgemm<<<dim3(L / 128, 1, B), 256>>>(Uid);
    k_final<<<dim3(2, L / BM, B), 256>>>(Uid, out);
}

// round 4
// speedup vs baseline: 3.5283x; 2.7445x over previous
#include <cuda_runtime.h>
#include <cstdint>
#include <cstddef>

#define B 8
#define L 2048
#define E 128
#define KC 32

// ---------------- scratch (device globals) ----------------------------------
__device__ float g_S[(size_t)B * L * L];      // exp(S*mask), tf32-rounded
__device__ float g_TT[(size_t)B * E * L];     // TT[e][j] = invd[j]^2 * sum_i Uid[i,e] expS[i,j]
__device__ float g_UqsT[(size_t)B * E * L];   // UqsT[e][j] = invd[j] * Uq[j,e]  (tf32)
__device__ float g_UidT[(size_t)B * E * L];   // UidT[e][i] = Uid[i,e]           (tf32)
__device__ float g_sid[B * L];
__device__ float g_sq[B * L];
__device__ float g_d[B * L];
__device__ float g_invd[B * L];

// ---------------- helpers ----------------------------------------------------
__device__ __forceinline__ float tf32r(float x) {
    uint32_t u;
    asm("cvt.rna.tf32.f32 %0, %1;" : "=r"(u) : "f"(x));
    return __uint_as_float(u);
}
__device__ __forceinline__ uint32_t smem_u32(const void* p) {
    uint32_t a;
    asm("{ .reg .u64 t; cvta.to.shared.u64 t, %1; cvt.u32.u64 %0, t; }"
        : "=r"(a) : "l"(p));
    return a;
}
__device__ __forceinline__ void ldsm4(uint32_t addr, uint32_t r[4]) {
    asm volatile("ldmatrix.sync.aligned.m8n8.x4.shared.b16 {%0,%1,%2,%3}, [%4];"
                 : "=r"(r[0]), "=r"(r[1]), "=r"(r[2]), "=r"(r[3]) : "r"(addr));
}
__device__ __forceinline__ void mma1688(float c[4], const uint32_t a[4],
                                        uint32_t b0, uint32_t b1) {
    asm volatile(
        "mma.sync.aligned.m16n8k8.row.col.f32.tf32.tf32.f32 "
        "{%0,%1,%2,%3}, {%4,%5,%6,%7}, {%8,%9}, {%0,%1,%2,%3};"
        : "+f"(c[0]), "+f"(c[1]), "+f"(c[2]), "+f"(c[3])
        : "r"(a[0]), "r"(a[1]), "r"(a[2]), "r"(a[3]), "r"(b0), "r"(b1));
}

// ---------------- cp.async ---------------------------------------------------
__device__ __forceinline__ void cpa16(uint32_t dst, const float* src) {
    asm volatile("cp.async.cg.shared.global [%0], [%1], 16;"
                 :: "r"(dst), "l"(src) : "memory");
}
__device__ __forceinline__ void cpa_commit() {
    asm volatile("cp.async.commit_group;" ::: "memory");
}
__device__ __forceinline__ void cpa_wait1() {
    asm volatile("cp.async.wait_group 1;" ::: "memory");
}
__device__ __forceinline__ void cpa_wait0() {
    asm volatile("cp.async.wait_group 0;" ::: "memory");
}

// ---------------- kernel 1: row dots s_id, s_q + zero g_d -------------------
__global__ void k_dots(const float* __restrict__ Uq,
                       const float* __restrict__ Uid,
                       const float* __restrict__ Wc_w) {
    int r = blockIdx.x * 8 + threadIdx.y;
    int lane = threadIdx.x;
    float sid = 0.f, sq = 0.f;
#pragma unroll
    for (int t = 0; t < 4; t++) {
        int e = lane + t * 32;
        sid += Uid[(size_t)r * E + e] * Wc_w[e];
        sq  += Uq [(size_t)r * E + e] * Wc_w[E + e];
    }
#pragma unroll
    for (int o = 16; o; o >>= 1) {
        sid += __shfl_xor_sync(0xffffffffu, sid, o);
        sq  += __shfl_xor_sync(0xffffffffu, sq,  o);
    }
    if (lane == 0) { g_sid[r] = sid; g_sq[r] = sq; g_d[r] = 0.f; }
}

// ---------------- kernel 2: expS + column sums, tf32 mma --------------------
// S = ((Uid*wmul) @ Uq^T + sid + sq + b) * mask; store exp(S) (tf32-rounded);
// accumulate column sums into g_d.  K=128 single-shot smem.
#define SGP 132
__global__ __launch_bounds__(256, 1) void k_sgemm(const float* __restrict__ Uq,
                                                  const float* __restrict__ Uid,
                                                  const float* __restrict__ mask,
                                                  const float* __restrict__ Wc_w,
                                                  const float* __restrict__ Wc_b) {
    extern __shared__ float sm[];
    float* As = sm;                 // [128][SGP]
    float* Bs = sm + 128 * SGP;     // [128][SGP]
    float* red = Bs + 128 * SGP;    // [128]
    int b  = blockIdx.z;
    int i0 = blockIdx.y * 128;
    int j0 = blockIdx.x * 128;
    const float* A  = Uid + (size_t)b * L * E;
    const float* Bq = Uq  + (size_t)b * L * E;
    const float* wmul = Wc_w + 2 * E;
    int tid = threadIdx.x, lane = tid & 31, wid = tid >> 5;
    int wm = wid & 3, wn = wid >> 2;            // 4 x 2 warps, tile 32m x 64n

    if (tid < 128) red[tid] = 0.f;

#pragma unroll
    for (int p = 0; p < 16; p++) {
        int idx = tid + p * 256;
        int row = idx >> 5, c = (idx & 31) * 4;
        float4 va = *(const float4*)&A[(size_t)(i0 + row) * E + c];
        float4 w  = *(const float4*)&wmul[c];
        As[row * SGP + c]     = tf32r(va.x * w.x);
        As[row * SGP + c + 1] = tf32r(va.y * w.y);
        As[row * SGP + c + 2] = tf32r(va.z * w.z);
        As[row * SGP + c + 3] = tf32r(va.w * w.w);
        float4 vb = *(const float4*)&Bq[(size_t)(j0 + row) * E + c];
        Bs[row * SGP + c]     = tf32r(vb.x);
        Bs[row * SGP + c + 1] = tf32r(vb.y);
        Bs[row * SGP + c + 2] = tf32r(vb.z);
        Bs[row * SGP + c + 3] = tf32r(vb.w);
    }
    __syncthreads();

    float acc[2][8][4];
#pragma unroll
    for (int mi = 0; mi < 2; mi++)
#pragma unroll
        for (int nt = 0; nt < 8; nt++)
#pragma unroll
            for (int q = 0; q < 4; q++) acc[mi][nt][q] = 0.f;

    uint32_t aBase = smem_u32(As), bBase = smem_u32(Bs);
    int fr = (lane & 15) * SGP + (lane >> 4) * 4;   // fragment row/col offset
#pragma unroll
    for (int kk = 0; kk < 16; kk++) {
        uint32_t a[2][4], bf[4][4];
#pragma unroll
        for (int mi = 0; mi < 2; mi++)
            ldsm4(aBase + ((wm * 32 + mi * 16) * SGP + kk * 8 + fr) * 4, a[mi]);
#pragma unroll
        for (int n4 = 0; n4 < 4; n4++)
            ldsm4(bBase + ((wn * 64 + n4 * 16) * SGP + kk * 8 + fr) * 4, bf[n4]);
#pragma unroll
        for (int n4 = 0; n4 < 4; n4++)
#pragma unroll
            for (int h = 0; h < 2; h++)
#pragma unroll
                for (int mi = 0; mi < 2; mi++)
                    mma1688(acc[mi][n4 * 2 + h], a[mi], bf[n4][h], bf[n4][h + 2]);
    }

    float bias = *Wc_b;
    float* Sout = g_S + (size_t)b * L * L;
    float cs0[8], cs1[8];
#pragma unroll
    for (int nt = 0; nt < 8; nt++) { cs0[nt] = 0.f; cs1[nt] = 0.f; }
#pragma unroll
    for (int mi = 0; mi < 2; mi++) {
        int r0 = i0 + wm * 32 + mi * 16 + (lane >> 2);
        float sidv0 = g_sid[b * L + r0];
        float sidv1 = g_sid[b * L + r0 + 8];
#pragma unroll
        for (int nt = 0; nt < 8; nt++) {
            int n = j0 + wn * 64 + nt * 8 + (lane & 3) * 2;
            float2 sq2 = *(const float2*)&g_sq[b * L + n];
            float2 mk0 = *(const float2*)&mask[(size_t)r0 * L + n];
            float2 mk1 = *(const float2*)&mask[(size_t)(r0 + 8) * L + n];
            float e0 = tf32r(__expf((acc[mi][nt][0] + sidv0 + sq2.x + bias) * mk0.x));
            float e1 = tf32r(__expf((acc[mi][nt][1] + sidv0 + sq2.y + bias) * mk0.y));
            float e2 = tf32r(__expf((acc[mi][nt][2] + sidv1 + sq2.x + bias) * mk1.x));
            float e3 = tf32r(__expf((acc[mi][nt][3] + sidv1 + sq2.y + bias) * mk1.y));
            *(float2*)&Sout[(size_t)r0 * L + n]       = make_float2(e0, e1);
            *(float2*)&Sout[(size_t)(r0 + 8) * L + n] = make_float2(e2, e3);
            cs0[nt] += e0 + e2;
            cs1[nt] += e1 + e3;
        }
    }
    // reduce across lanes sharing the same columns (lane>>2 varies)
#pragma unroll
    for (int o = 16; o >= 4; o >>= 1)
#pragma unroll
        for (int nt = 0; nt < 8; nt++) {
            cs0[nt] += __shfl_xor_sync(0xffffffffu, cs0[nt], o);
            cs1[nt] += __shfl_xor_sync(0xffffffffu, cs1[nt], o);
        }
    if ((lane >> 2) == 0) {
#pragma unroll
        for (int nt = 0; nt < 8; nt++) {
            int nl = wn * 64 + nt * 8 + (lane & 3) * 2;
            atomicAdd(&red[nl], cs0[nt]);
            atomicAdd(&red[nl + 1], cs1[nt]);
        }
    }
    __syncthreads();
    if (tid < 128) atomicAdd(&g_d[(size_t)b * L + j0 + tid], red[tid]);
}

// ---------------- kernel 3: invd = 1/d --------------------------------------
__global__ void k_inv() {
    int r = blockIdx.x * 256 + threadIdx.x;
    g_invd[r] = 1.0f / g_d[r];
}

// ---------------- kernel 4: transposes -> tf32  Uid->UidT, invd*Uq->UqsT ----
__global__ void k_trans(const float* __restrict__ Uid,
                        const float* __restrict__ Uq) {
    __shared__ float t[32][33];
    int l0 = blockIdx.x * 32, e0 = blockIdx.y * 32;
    int b = blockIdx.z >> 1, mat = blockIdx.z & 1;
    const float* src = (mat ? Uq : Uid) + (size_t)b * L * E;
    int tx = threadIdx.x, ty = threadIdx.y;
#pragma unroll
    for (int r = 0; r < 4; r++)
        t[ty + r * 8][tx] = src[(size_t)(l0 + ty + r * 8) * E + e0 + tx];
    __syncthreads();
    float inv = mat ? g_invd[b * L + l0 + tx] : 1.0f;
    float* dst = (mat ? g_UqsT : g_UidT) + (size_t)b * E * L;
#pragma unroll
    for (int r = 0; r < 4; r++)
        dst[(size_t)(e0 + ty + r * 8) * L + l0 + tx] = tf32r(t[tx][ty + r * 8] * inv);
}

// ---------------- kernel 5: TT = invd^2 * (UidT @ expS)   tf32 mma ----------
// A = UidT[e][i] direct (pitch 36, ldmatrix); B = expS[i][j] direct in
// Bs[k][n] layout (pitch 136) with scalar-LDS fragments (conflict-free).
#define TAP 36
#define TBP 136
__global__ __launch_bounds__(256, 1) void k_tgemm2() {
    extern __shared__ float sm[];
    float* As = sm;                       // [2][128][TAP]
    float* Bs = sm + 2 * 128 * TAP;       // [2][32][TBP]
    const int stA = 128 * TAP, stB = KC * TBP;
    int tid = threadIdx.x, lane = tid & 31, wid = tid >> 5;
    int wm = wid & 3, wn = wid >> 2;      // 4 x 2, warp tile 32m x 64n
    int b = blockIdx.y;
    int j0 = blockIdx.x * 128;
    const float* Ab = g_UidT + (size_t)b * E * L;
    const float* Sb = g_S + (size_t)b * L * L;

    uint32_t aBase = smem_u32(As), bBase = smem_u32(Bs);

    auto load = [&](int s, int t) {
        int k0 = t * KC;
#pragma unroll
        for (int p = 0; p < 4; p++) {
            int idx = tid + p * 256;
            int row = idx >> 3, q = (idx & 7) * 4;
            cpa16(aBase + (s * stA + row * TAP + q) * 4, &Ab[(size_t)row * L + k0 + q]);
        }
#pragma unroll
        for (int p = 0; p < 4; p++) {
            int idx = tid + p * 256;
            int i = idx >> 5, j4 = (idx & 31) * 4;
            cpa16(bBase + (s * stB + i * TBP + j4) * 4,
                  &Sb[(size_t)(k0 + i) * L + j0 + j4]);
        }
        cpa_commit();
    };

    float acc[2][8][4];
#pragma unroll
    for (int mi = 0; mi < 2; mi++)
#pragma unroll
        for (int nt = 0; nt < 8; nt++)
#pragma unroll
            for (int q = 0; q < 4; q++) acc[mi][nt][q] = 0.f;

    int frA = (lane & 15) * TAP + (lane >> 4) * 4;
    load(0, 0);
    const int iters = L / KC;
    for (int t = 0; t < iters; t++) {
        int s = t & 1;
        if (t + 1 < iters) { load(s ^ 1, t + 1); cpa_wait1(); }
        else               { cpa_wait0(); }
        __syncthreads();
        const float* Bss = Bs + s * stB;
#pragma unroll
        for (int kk = 0; kk < 4; kk++) {
            uint32_t a[2][4];
#pragma unroll
            for (int mi = 0; mi < 2; mi++)
                ldsm4(aBase + (s * stA + (wm * 32 + mi * 16) * TAP + kk * 8 + frA) * 4, a[mi]);
#pragma unroll
            for (int nt = 0; nt < 8; nt++) {
                const float* bp = &Bss[(kk * 8 + (lane & 3)) * TBP +
                                       wn * 64 + nt * 8 + (lane >> 2)];
                uint32_t b0 = __float_as_uint(bp[0]);
                uint32_t b1 = __float_as_uint(bp[4 * TBP]);
#pragma unroll
                for (int mi = 0; mi < 2; mi++) mma1688(acc[mi][nt], a[mi], b0, b1);
            }
        }
        __syncthreads();
    }

#pragma unroll
    for (int mi = 0; mi < 2; mi++) {
        int e0r = wm * 32 + mi * 16 + (lane >> 2);
#pragma unroll
        for (int nt = 0; nt < 8; nt++) {
            int j = j0 + wn * 64 + nt * 8 + (lane & 3) * 2;
            float2 iv = *(const float2*)&g_invd[b * L + j];
            float s0 = iv.x * iv.x, s1 = iv.y * iv.y;
            float* d0 = &g_TT[((size_t)b * E + e0r) * L + j];
            float* d1 = &g_TT[((size_t)b * E + e0r + 8) * L + j];
            *(float2*)d0 = make_float2(tf32r(acc[mi][nt][0] * s0), tf32r(acc[mi][nt][1] * s1));
            *(float2*)d1 = make_float2(tf32r(acc[mi][nt][2] * s0), tf32r(acc[mi][nt][3] * s1));
        }
    }
}

// ---------------- kernel 6: [A_D2Q | A_Q2D] = expS @ [UqsT | TT]^T ----------
// CTA 128m x 256n, 512 threads (4m x 4n warps, warp tile 32x64).
__global__ __launch_bounds__(512, 1) void k_final(const float* __restrict__ Uid,
                                                  float* __restrict__ out) {
    extern __shared__ float sm[];
    float* As = sm;                       // [2][128][TAP]
    float* Bs = sm + 2 * 128 * TAP;       // [2][256][TAP]
    const int stA = 128 * TAP, stB = 256 * TAP;
    int tid = threadIdx.x, lane = tid & 31, wid = tid >> 5;
    int wm = wid & 3, wn = wid >> 2;      // 4 x 4
    int b = blockIdx.y;
    int i0 = blockIdx.x * 128;
    const float* Sb  = g_S    + (size_t)b * L * L + (size_t)i0 * L;
    const float* B1g = g_UqsT + (size_t)b * E * L;
    const float* B2g = g_TT   + (size_t)b * E * L;

    uint32_t aBase = smem_u32(As), bBase = smem_u32(Bs);

    auto load = [&](int s, int t) {
        int k0 = t * KC;
#pragma unroll
        for (int p = 0; p < 2; p++) {
            int idx = tid + p * 512;
            int row = idx >> 3, q = (idx & 7) * 4;
            cpa16(aBase + (s * stA + row * TAP + q) * 4, &Sb[(size_t)row * L + k0 + q]);
        }
#pragma unroll
        for (int p = 0; p < 4; p++) {
            int idx = tid + p * 512;
            int row = idx >> 3, q = (idx & 7) * 4;
            const float* src = row < 128 ? &B1g[(size_t)row * L + k0 + q]
                                         : &B2g[(size_t)(row - 128) * L + k0 + q];
            cpa16(bBase + (s * stB + row * TAP + q) * 4, src);
        }
        cpa_commit();
    };

    float acc[2][8][4];
#pragma unroll
    for (int mi = 0; mi < 2; mi++)
#pragma unroll
        for (int nt = 0; nt < 8; nt++)
#pragma unroll
            for (int q = 0; q < 4; q++) acc[mi][nt][q] = 0.f;

    int fr = (lane & 15) * TAP + (lane >> 4) * 4;
    load(0, 0);
    const int iters = L / KC;
    for (int t = 0; t < iters; t++) {
        int s = t & 1;
        if (t + 1 < iters) { load(s ^ 1, t + 1); cpa_wait1(); }
        else               { cpa_wait0(); }
        __syncthreads();
#pragma unroll
        for (int kk = 0; kk < 4; kk++) {
            uint32_t a[2][4], bf[4][4];
#pragma unroll
            for (int mi = 0; mi < 2; mi++)
                ldsm4(aBase + (s * stA + (wm * 32 + mi * 16) * TAP + kk * 8 + fr) * 4, a[mi]);
#pragma unroll
            for (int n4 = 0; n4 < 4; n4++)
                ldsm4(bBase + (s * stB + (wn * 64 + n4 * 16) * TAP + kk * 8 + fr) * 4, bf[n4]);
#pragma unroll
            for (int n4 = 0; n4 < 4; n4++)
#pragma unroll
                for (int h = 0; h < 2; h++)
#pragma unroll
                    for (int mi = 0; mi < 2; mi++)
                        mma1688(acc[mi][n4 * 2 + h], a[mi], bf[n4][h], bf[n4][h + 2]);
        }
        __syncthreads();
    }

    // epilogue: out row i: [Uid | A_D2Q | Uid*A_D2Q | Uid*A_Q2D]
#pragma unroll
    for (int mi = 0; mi < 2; mi++) {
        int r0 = i0 + wm * 32 + mi * 16 + (lane >> 2);
#pragma unroll
        for (int nt = 0; nt < 8; nt++) {
            int n = wn * 64 + nt * 8 + (lane & 3) * 2;   // 0..255
#pragma unroll
            for (int h = 0; h < 2; h++) {
                int gi = r0 + h * 8;
                float v0 = acc[mi][nt][h * 2], v1 = acc[mi][nt][h * 2 + 1];
                float* orow = out + ((size_t)b * L + gi) * (4 * E);
                if (n < 128) {
                    float2 u = *(const float2*)&Uid[((size_t)b * L + gi) * E + n];
                    *(float2*)&orow[128 + n] = make_float2(v0, v1);
                    *(float2*)&orow[256 + n] = make_float2(v0 * u.x, v1 * u.y);
                } else {
                    int m = n - 128;
                    float2 u = *(const float2*)&Uid[((size_t)b * L + gi) * E + m];
                    *(float2*)&orow[384 + m] = make_float2(v0 * u.x, v1 * u.y);
                }
            }
        }
    }
    // Uid copy into slot 0
#pragma unroll
    for (int p = 0; p < 8; p++) {
        int idx = tid + p * 512;
        int row = idx >> 5, c = (idx & 31) * 4;
        int gi = i0 + row;
        *(float4*)&out[((size_t)b * L + gi) * (4 * E) + c] =
            *(const float4*)&Uid[((size_t)b * L + gi) * E + c];
    }
}

// ---------------- launch ----------------------------------------------------
extern "C" void kernel_launch(void* const* d_in, const int* in_sizes, int n_in,
                              void* d_out, int out_size) {
    const float* Uq   = (const float*)d_in[0];
    const float* Uid  = (const float*)d_in[1];
    const float* mask = (const float*)d_in[2];
    const float* Wc_w = (const float*)d_in[3];
    const float* Wc_b = (const float*)d_in[4];
    float* out = (float*)d_out;

    const int SMEM_SG = (128 * SGP * 2 + 128) * 4;                 // 135680
    const int SMEM_TG = (2 * 128 * TAP + 2 * KC * TBP) * 4;        // 71680
    const int SMEM_FI = (2 * 128 * TAP + 2 * 256 * TAP) * 4;       // 110592
    cudaFuncSetAttribute(k_sgemm,  cudaFuncAttributeMaxDynamicSharedMemorySize, SMEM_SG);
    cudaFuncSetAttribute(k_tgemm2, cudaFuncAttributeMaxDynamicSharedMemorySize, SMEM_TG);
    cudaFuncSetAttribute(k_final,  cudaFuncAttributeMaxDynamicSharedMemorySize, SMEM_FI);

    k_dots<<<(B * L) / 8, dim3(32, 8)>>>(Uq, Uid, Wc_w);
    k_sgemm<<<dim3(L / 128, L / 128, B), 256, SMEM_SG>>>(Uq, Uid, mask, Wc_w, Wc_b);
    k_inv<<<(B * L) / 256, 256>>>();
    k_trans<<<dim3(L / 32, E / 32, 2 * B), dim3(32, 8)>>>(Uid, Uq);
    k_tgemm2<<<dim3(L / 128, B), 256, SMEM_TG>>>();
    k_final<<<dim3(L / 128, B), 512, SMEM_FI>>>(Uid, out);
}